// round 9
// baseline (speedup 1.0000x reference)
#include <cuda_runtime.h>

#define BB 256
#define SS 4096
#define HH 64
#define NG 256   // 4*H gates

// Scratch (allocation-free: static device globals)
__device__ float g_buf0[(size_t)BB * SS * HH];
__device__ float g_buf1[(size_t)BB * SS * HH];
__device__ float g_xg[(size_t)BB * SS * NG];   // gate-interleaved: [b,s,hh*4+q]

typedef unsigned long long ull;

// ---- packed f32x2 helpers (FFMA2 path, sm_103a) ----
__device__ __forceinline__ ull pk2(float lo, float hi) {
    ull r; asm("mov.b64 %0,{%1,%2};" : "=l"(r) : "f"(lo), "f"(hi)); return r;
}
__device__ __forceinline__ void upk2(ull v, float& lo, float& hi) {
    asm("mov.b64 {%0,%1},%2;" : "=f"(lo), "=f"(hi) : "l"(v));
}
__device__ __forceinline__ ull ffma2(ull a, ull b, ull c) {
    ull d; asm("fma.rn.f32x2 %0,%1,%2,%3;" : "=l"(d) : "l"(a), "l"(b), "l"(c)); return d;
}

// sigmoid via MUFU (err ~1e-6). tanh(x) = 2*sig(2x)-1 (exact identity).
__device__ __forceinline__ float sig_(float x) {
    float e = __expf(-x);
    return __fdividef(1.f, 1.f + e);
}
__device__ __forceinline__ float tanh_(float x) {
    return 2.f * sig_(2.f * x) - 1.f;
}

// Named barrier over one batch's 256 threads (8 warps). ids 1,2.
#define BATCH_BAR(bl) asm volatile("bar.sync %0, 256;" :: "r"((bl) + 1) : "memory")

// ============================================================================
// xgemm: unchanged from R5/R8 (best known).
// ============================================================================
__global__ __launch_bounds__(256, 1)
void xgemm(const float* __restrict__ hs, const float* __restrict__ Wih,
           const float* __restrict__ bih, const float* __restrict__ bhh,
           float* __restrict__ xg) {
    const int gq = threadIdx.x;
    const int q = gq & 3, hh = gq >> 2;
    const int row = q * HH + hh;
    const int b0 = (blockIdx.x >> 1) * 2;
    const int s0 = (blockIdx.x & 1) * (SS / 2);

    __shared__ float4 sh[2][16][16];   // [parity][chunk row][16 float4]

    ull w[32];
    {
        const float4* Wr = reinterpret_cast<const float4*>(Wih + row * HH);
#pragma unroll
        for (int k = 0; k < 16; k++) {
            float4 v = Wr[k];
            w[2 * k] = pk2(v.x, v.y);
            w[2 * k + 1] = pk2(v.z, v.w);
        }
    }
    const float bias = bih[row] + bhh[row];

    const int bb = gq >> 7, so = (gq >> 4) & 7, qq = gq & 15;
    const size_t ldb = ((size_t)(b0 + bb) * SS + s0 + so) * 16 + qq;  // float4 units
    const float4* hs4 = reinterpret_cast<const float4*>(hs);

    sh[0][bb * 8 + so][qq] = hs4[ldb];   // prime chunk 0

    int p = 0;
    const int NCH = (SS / 2) / 8;  // 256 chunks
    for (int ch = 0; ch < NCH; ++ch) {
        __syncthreads();
        float4 nxt;
        if (ch + 1 < NCH) nxt = hs4[ldb + (size_t)(ch + 1) * 128];

#pragma unroll
        for (int rp = 0; rp < 8; ++rp) {
            const int r0 = 2 * rp, r1 = r0 + 1;
            ull a0 = pk2(bias, 0.f);
            ull a1 = pk2(bias, 0.f);
            const ulonglong2* v0 = reinterpret_cast<const ulonglong2*>(sh[p][r0]);
            const ulonglong2* v1 = reinterpret_cast<const ulonglong2*>(sh[p][r1]);
#pragma unroll
            for (int k = 0; k < 16; k++) {
                ulonglong2 p0 = v0[k];
                ulonglong2 p1 = v1[k];
                a0 = ffma2(w[2 * k], p0.x, a0);
                a0 = ffma2(w[2 * k + 1], p0.y, a0);
                a1 = ffma2(w[2 * k], p1.x, a1);
                a1 = ffma2(w[2 * k + 1], p1.y, a1);
            }
            float l, h;
            upk2(a0, l, h); float sA = l + h;
            upk2(a1, l, h); float sB = l + h;
            xg[((size_t)(b0 + (r0 >> 3)) * SS + s0 + (size_t)ch * 8 + (r0 & 7)) * NG + gq] = sA;
            xg[((size_t)(b0 + (r1 >> 3)) * SS + s0 + (size_t)ch * 8 + (r1 & 7)) * NG + gq] = sB;
        }
        if (ch + 1 < NCH) sh[p ^ 1][bb * 8 + so][qq] = nxt;
        p ^= 1;
    }
}

// ============================================================================
// LSTM scan, K-SPLIT edition. 128 CTAs x 512 threads, 2 batches/CTA.
// Thread j = b*256 + hh*4 + ks*2 + p:
//   owns rows {p*128+hh, p*128+64+hh} over k-half [ks*32, ks*32+32).
// vs R8: warps/SMSP 2->4, chain depth 32->16, LDS bytes UNCHANGED (each
// thread loads only its k-half of h), weight regs 128->64.
// Partial sums combined with shfl_xor(2); gate pair exchange shfl_xor(1).
// Per-batch named barrier (256 thr). x loads on ks==0 lanes only.
// ============================================================================
template <bool L0>
__global__ __launch_bounds__(512, 1)
void lstm_scan(const float* __restrict__ xin,   // L0: x [B,S,1]; else xg [B,S,256]
               const float* __restrict__ Wih,   // L0 only: [256,1]
               const float* __restrict__ Whh,
               const float* __restrict__ bih, const float* __restrict__ bhh,
               float* __restrict__ hsout,
               float* __restrict__ hn, float* __restrict__ cn) {
    const int j = threadIdx.x;
    const int b = j >> 8;            // local batch 0/1
    const int r = j & 255;
    const int hh = r >> 2;
    const int ks = (r >> 1) & 1;     // k-half
    const int p = r & 1;             // gate pair: 0 -> (i,f), 1 -> (g,o)
    const int row0 = p * 128 + hh;
    const int row1 = row0 + 64;
    const int bg = blockIdx.x * 2 + b;   // global batch

    __shared__ float4 sh_h[2][2][16];   // [parity][b][64 floats]

    // ---- weights: k-half of two rows (16 ull = 32 regs... x2 rows = 32 ull) ----
    ull wA[16], wB[16];
    {
        const float4* Wr = reinterpret_cast<const float4*>(Whh + row0 * HH + ks * 32);
#pragma unroll
        for (int k = 0; k < 8; k++) {
            float4 v = Wr[k];
            wA[2 * k] = pk2(v.x, v.y);
            wA[2 * k + 1] = pk2(v.z, v.w);
        }
        const float4* Wr2 = reinterpret_cast<const float4*>(Whh + row1 * HH + ks * 32);
#pragma unroll
        for (int k = 0; k < 8; k++) {
            float4 v = Wr2[k];
            wB[2 * k] = pk2(v.x, v.y);
            wB[2 * k + 1] = pk2(v.z, v.w);
        }
    }
    float w0A = 0.f, w0B = 0.f, biasA = 0.f, biasB = 0.f;
    if (L0) {
        w0A = Wih[row0]; w0B = Wih[row1];
        biasA = bih[row0] + bhh[row0];
        biasB = bih[row1] + bhh[row1];
    }
    // activation: A = m*sig(m*g) - d   (p1 row0 is the 'g' gate -> tanh)
    const float m0 = (p == 1) ? 2.f : 1.f;
    const float d0 = (p == 1) ? 1.f : 0.f;

    // zero h parity 0 (both batches)
    if (j < 32) reinterpret_cast<float4*>(sh_h)[j] = make_float4(0.f, 0.f, 0.f, 0.f);

    // ---- x stream: ks==0 lanes only, depth-2 register prefetch ----
    float  xcs = 0.f, xns = 0.f;
    float2 xc2 = make_float2(0.f, 0.f), xn2 = xc2;
    const float*  xps = nullptr;
    const float2* xp2 = nullptr;
    if (L0) {
        if (ks == 0) {
            const float* xbase = xin + (size_t)bg * SS;
            xcs = xbase[0];
            xns = xbase[1];
            xps = xbase + 2;
        }
    } else {
        if (ks == 0) {
            const float2* xbase = reinterpret_cast<const float2*>(xin)
                                  + ((size_t)bg * SS) * 128 + hh * 2 + p;
            xc2 = xbase[0];
            xn2 = xbase[128];
            xp2 = xbase + 256;
        }
    }
    __syncthreads();

    float c = 0.f;

    for (int t = 0; t < SS; ++t) {
        const int pr = t & 1;

        // prefetch t+2 (ks==0 lanes)
        float  pfs = 0.f;
        float2 pf2 = make_float2(0.f, 0.f);
        if (ks == 0) {
            if (L0) { if (t + 2 < SS) pfs = *xps; xps += 1; }
            else    { if (t + 2 < SS) pf2 = *xp2; xp2 += 128; }
        }

        // ax seeds (ks==0 lanes carry ax; ks==1 seed 0)
        float axA = 0.f, axB = 0.f;
        if (ks == 0) {
            if (L0) { axA = fmaf(w0A, xcs, biasA); axB = fmaf(w0B, xcs, biasB); }
            else    { axA = xc2.x; axB = xc2.y; }
        }

        // ---- partial dot over own k-half: burst preload (MLP 8) + chains ----
        ull a0 = pk2(axA, 0.f);
        ull a1 = pk2(axB, 0.f);
        {
            const ulonglong2* vh = reinterpret_cast<const ulonglong2*>(sh_h[pr][b]) + ks * 8;
            ulonglong2 hb[8];
#pragma unroll
            for (int k = 0; k < 8; k++) hb[k] = vh[k];
#pragma unroll
            for (int k = 0; k < 8; k++) {
                a0 = ffma2(wA[2 * k], hb[k].x, a0);
                a0 = ffma2(wA[2 * k + 1], hb[k].y, a0);
                a1 = ffma2(wB[2 * k], hb[k].x, a1);
                a1 = ffma2(wB[2 * k + 1], hb[k].y, a1);
            }
        }
        float l, h;
        upk2(a0, l, h); float s0 = l + h;
        upk2(a1, l, h); float s1 = l + h;

        // combine k-halves (commutative add -> bitwise-identical in both lanes)
        float g0 = s0 + __shfl_xor_sync(0xffffffffu, s0, 2);
        float g1 = s1 + __shfl_xor_sync(0xffffffffu, s1, 2);

        // activations: p0 -> (i,f) sigmoids; p1 -> (g tanh, o sigmoid)
        float A0 = m0 * sig_(m0 * g0) - d0;
        float A1 = sig_(g1);

        // gate pair exchange
        float B0 = __shfl_xor_sync(0xffffffffu, A0, 1);
        float B1 = __shfl_xor_sync(0xffffffffu, A1, 1);
        float iv, fv, gv, ov;
        if (p == 0) { iv = A0; fv = A1; gv = B0; ov = B1; }
        else        { iv = B0; fv = B1; gv = A0; ov = A1; }

        // redundant identical update in all 4 (p,ks) lanes
        c = fv * c + iv * gv;
        float hv2 = ov * tanh_(c);

        if (ks == 0) {
            if (p == 0) {
                reinterpret_cast<float*>(sh_h[pr ^ 1][b])[hh] = hv2;
            } else {
                hsout[((size_t)bg * SS + t) * HH + hh] = hv2;
            }
        } else if (t == SS - 1) {
            if (p == 0) cn[bg * HH + hh] = c;
            else        hn[bg * HH + hh] = hv2;
        }
        BATCH_BAR(b);   // this batch's 8 warps; h_t visible for t+1

        if (ks == 0) {
            if (L0) { xcs = xns; xns = pfs; }
            else    { xc2 = xn2; xn2 = pf2; }
        }
    }
}

// Final projection: thread-per-output, 16 consecutive LDG.128 per thread.
__global__ __launch_bounds__(256)
void proj_kernel(const float* __restrict__ hs, const float* __restrict__ Wlin,
                 const float* __restrict__ blin, float* __restrict__ y) {
    __shared__ float4 w[16];
    __shared__ float bsh;
    if (threadIdx.x < 16) w[threadIdx.x] = reinterpret_cast<const float4*>(Wlin)[threadIdx.x];
    if (threadIdx.x == 16) bsh = blin[0];
    __syncthreads();
    size_t o = (size_t)blockIdx.x * 256 + threadIdx.x;
    const float4* v = reinterpret_cast<const float4*>(hs + o * HH);
    float acc = 0.f;
#pragma unroll
    for (int k = 0; k < 16; k++) {
        float4 a = v[k];
        float4 b = w[k];
        acc += a.x * b.x + a.y * b.y + a.z * b.z + a.w * b.w;
    }
    y[o] = acc + bsh;
}

extern "C" void kernel_launch(void* const* d_in, const int* in_sizes, int n_in,
                              void* d_out, int out_size) {
    const float* x    = (const float*)d_in[0];
    const float* Wih0 = (const float*)d_in[1];
    const float* Whh0 = (const float*)d_in[2];
    const float* bih0 = (const float*)d_in[3];
    const float* bhh0 = (const float*)d_in[4];
    const float* Wih1 = (const float*)d_in[5];
    const float* Whh1 = (const float*)d_in[6];
    const float* bih1 = (const float*)d_in[7];
    const float* bhh1 = (const float*)d_in[8];
    const float* Wih2 = (const float*)d_in[9];
    const float* Whh2 = (const float*)d_in[10];
    const float* bih2 = (const float*)d_in[11];
    const float* bhh2 = (const float*)d_in[12];
    const float* Wlin = (const float*)d_in[13];
    const float* blin = (const float*)d_in[14];

    float* y  = (float*)d_out;                 // [B,S,1]
    float* hn = y + (size_t)BB * SS;           // [3,B,H]
    float* cn = hn + (size_t)3 * BB * HH;      // [3,B,H]

    float *buf0, *buf1, *xg;
    cudaGetSymbolAddress((void**)&buf0, g_buf0);
    cudaGetSymbolAddress((void**)&buf1, g_buf1);
    cudaGetSymbolAddress((void**)&xg,  g_xg);

    // Layer 0: inline scalar x (DIN=1)
    lstm_scan<true ><<<BB / 2, 512>>>(x, Wih0, Whh0, bih0, bhh0, buf0, hn, cn);
    // Layer 1: precompute interleaved xg, then h-only scan
    xgemm<<<BB, 256>>>(buf0, Wih1, bih1, bhh1, xg);
    lstm_scan<false><<<BB / 2, 512>>>(xg, Wih1, Whh1, bih1, bhh1, buf1,
                                      hn + BB * HH, cn + BB * HH);
    // Layer 2
    xgemm<<<BB, 256>>>(buf1, Wih2, bih2, bhh2, xg);
    lstm_scan<false><<<BB / 2, 512>>>(xg, Wih2, Whh2, bih2, bhh2, buf0,
                                      hn + 2 * BB * HH, cn + 2 * BB * HH);

    proj_kernel<<<(BB * SS) / 256, 256>>>(buf0, Wlin, blin, y);
}

// round 10
// speedup vs baseline: 1.6887x; 1.6887x over previous
#include <cuda_runtime.h>

#define BB 256
#define SS 4096
#define HH 64
#define NG 256   // 4*H gates

// Scratch (allocation-free: static device globals)
__device__ float g_buf0[(size_t)BB * SS * HH];
__device__ float g_buf1[(size_t)BB * SS * HH];
__device__ float g_xg[(size_t)BB * SS * NG];   // gate-interleaved: [b,s,hh*4+q]

typedef unsigned long long ull;

// ---- packed f32x2 helpers (FFMA2 path, sm_103a) ----
__device__ __forceinline__ ull pk2(float lo, float hi) {
    ull r; asm("mov.b64 %0,{%1,%2};" : "=l"(r) : "f"(lo), "f"(hi)); return r;
}
__device__ __forceinline__ void upk2(ull v, float& lo, float& hi) {
    asm("mov.b64 {%0,%1},%2;" : "=f"(lo), "=f"(hi) : "l"(v));
}
__device__ __forceinline__ ull ffma2(ull a, ull b, ull c) {
    ull d; asm("fma.rn.f32x2 %0,%1,%2,%3;" : "=l"(d) : "l"(a), "l"(b), "l"(c)); return d;
}

// sigmoid via MUFU (err ~1e-6). tanh(x) = 2*sig(2x)-1 (exact identity).
__device__ __forceinline__ float sig_(float x) {
    float e = __expf(-x);
    return __fdividef(1.f, 1.f + e);
}
__device__ __forceinline__ float tanh_(float x) {
    return 2.f * sig_(2.f * x) - 1.f;
}

// Named barrier over one batch's 128 threads (4 warps). ids 1,2.
#define BATCH_BAR(bl) asm volatile("bar.sync %0, 128;" :: "r"((bl) + 1) : "memory")

// ============================================================================
// xgemm: unchanged from R5/R8 (at the fp32 FFMA2 issue floor).
// ============================================================================
__global__ __launch_bounds__(256, 1)
void xgemm(const float* __restrict__ hs, const float* __restrict__ Wih,
           const float* __restrict__ bih, const float* __restrict__ bhh,
           float* __restrict__ xg) {
    const int gq = threadIdx.x;
    const int q = gq & 3, hh = gq >> 2;
    const int row = q * HH + hh;
    const int b0 = (blockIdx.x >> 1) * 2;
    const int s0 = (blockIdx.x & 1) * (SS / 2);

    __shared__ float4 sh[2][16][16];   // [parity][chunk row][16 float4]

    ull w[32];
    {
        const float4* Wr = reinterpret_cast<const float4*>(Wih + row * HH);
#pragma unroll
        for (int k = 0; k < 16; k++) {
            float4 v = Wr[k];
            w[2 * k] = pk2(v.x, v.y);
            w[2 * k + 1] = pk2(v.z, v.w);
        }
    }
    const float bias = bih[row] + bhh[row];

    const int bb = gq >> 7, so = (gq >> 4) & 7, qq = gq & 15;
    const size_t ldb = ((size_t)(b0 + bb) * SS + s0 + so) * 16 + qq;  // float4 units
    const float4* hs4 = reinterpret_cast<const float4*>(hs);

    sh[0][bb * 8 + so][qq] = hs4[ldb];   // prime chunk 0

    int p = 0;
    const int NCH = (SS / 2) / 8;  // 256 chunks
    for (int ch = 0; ch < NCH; ++ch) {
        __syncthreads();
        float4 nxt;
        if (ch + 1 < NCH) nxt = hs4[ldb + (size_t)(ch + 1) * 128];

#pragma unroll
        for (int rp = 0; rp < 8; ++rp) {
            const int r0 = 2 * rp, r1 = r0 + 1;
            ull a0 = pk2(bias, 0.f);
            ull a1 = pk2(bias, 0.f);
            const ulonglong2* v0 = reinterpret_cast<const ulonglong2*>(sh[p][r0]);
            const ulonglong2* v1 = reinterpret_cast<const ulonglong2*>(sh[p][r1]);
#pragma unroll
            for (int k = 0; k < 16; k++) {
                ulonglong2 p0 = v0[k];
                ulonglong2 p1 = v1[k];
                a0 = ffma2(w[2 * k], p0.x, a0);
                a0 = ffma2(w[2 * k + 1], p0.y, a0);
                a1 = ffma2(w[2 * k], p1.x, a1);
                a1 = ffma2(w[2 * k + 1], p1.y, a1);
            }
            float l, h;
            upk2(a0, l, h); float sA = l + h;
            upk2(a1, l, h); float sB = l + h;
            xg[((size_t)(b0 + (r0 >> 3)) * SS + s0 + (size_t)ch * 8 + (r0 & 7)) * NG + gq] = sA;
            xg[((size_t)(b0 + (r1 >> 3)) * SS + s0 + (size_t)ch * 8 + (r1 & 7)) * NG + gq] = sB;
        }
        if (ch + 1 < NCH) sh[p ^ 1][bb * 8 + so][qq] = nxt;
        p ^= 1;
    }
}

// ============================================================================
// LSTM scan = R8 champion (256 thr, 2 batches/CTA, 2 rows/thread, pair-shfl,
// per-batch named barriers) + serial-chain surgery:
//   * preload ALL 16 ulonglong2 of h (MLP 16)
//   * FOUR independent ffma2 chains of depth 16 (was 2 x depth 32)
//   * hsout/hn/cn stores moved AFTER the barrier (pre-bar path = STS only)
// ============================================================================
template <bool L0>
__global__ __launch_bounds__(256, 1)
void lstm_scan(const float* __restrict__ xin,   // L0: x [B,S,1]; else xg [B,S,256]
               const float* __restrict__ Wih,   // L0 only: [256,1]
               const float* __restrict__ Whh,
               const float* __restrict__ bih, const float* __restrict__ bhh,
               float* __restrict__ hsout,
               float* __restrict__ hn, float* __restrict__ cn) {
    const int j = threadIdx.x;
    const int p = j & 1;
    const int hh = (j >> 1) & 63;
    const int b = j >> 7;
    const int b0 = blockIdx.x * 2;
    const int row0 = p * 128 + hh;        // p0: i-row ; p1: g-row
    const int row1 = p * 128 + 64 + hh;   // p0: f-row ; p1: o-row

    __shared__ float4 sh_h[2][2][16];   // [parity][b][64 floats]

    ull wA[32], wB[32];
    {
        const float4* Wr = reinterpret_cast<const float4*>(Whh + row0 * HH);
#pragma unroll
        for (int k = 0; k < 16; k++) {
            float4 v = Wr[k];
            wA[2 * k] = pk2(v.x, v.y);
            wA[2 * k + 1] = pk2(v.z, v.w);
        }
        const float4* Wr2 = reinterpret_cast<const float4*>(Whh + row1 * HH);
#pragma unroll
        for (int k = 0; k < 16; k++) {
            float4 v = Wr2[k];
            wB[2 * k] = pk2(v.x, v.y);
            wB[2 * k + 1] = pk2(v.z, v.w);
        }
    }
    float w0A = 0.f, w0B = 0.f, biasA = 0.f, biasB = 0.f;
    if (L0) {
        w0A = Wih[row0]; w0B = Wih[row1];
        biasA = bih[row0] + bhh[row0];
        biasB = bih[row1] + bhh[row1];
    }
    // activation params: A = m*sig(m*g) - d  (m=2,d=1 for tanh on p1's g-row)
    const float m0 = (p == 1) ? 2.f : 1.f;
    const float d0 = (p == 1) ? 1.f : 0.f;

    // zero h parity 0 (both batches)
    if (j < 32) reinterpret_cast<float4*>(sh_h)[j] = make_float4(0.f, 0.f, 0.f, 0.f);

    // ---- x stream: depth-2 register prefetch, pointer-walk ----
    float  xcs = 0.f, xns = 0.f;                       // L0 scalar
    float2 xc2 = make_float2(0.f, 0.f), xn2 = xc2;     // !L0 packed pair
    const float*  xps = nullptr;
    const float2* xp2 = nullptr;
    if (L0) {
        const float* xbase = xin + (size_t)(b0 + b) * SS;
        xcs = xbase[0];
        xns = xbase[1];
        xps = xbase + 2;
    } else {
        const float2* xbase = reinterpret_cast<const float2*>(xin)
                              + ((size_t)(b0 + b) * SS) * 128 + hh * 2 + p;
        xc2 = xbase[0];
        xn2 = xbase[128];
        xp2 = xbase + 256;
    }
    __syncthreads();

    float c = 0.f;

    for (int t = 0; t < SS; ++t) {
        const int pr = t & 1;

        // ---- preload ALL of h (MLP 16) immediately after barrier ----
        ulonglong2 hb[16];
        {
            const ulonglong2* vh = reinterpret_cast<const ulonglong2*>(sh_h[pr][b]);
#pragma unroll
            for (int k = 0; k < 16; k++) hb[k] = vh[k];
        }

        // prefetch t+2 (pointer-walk, predicated tail) — overlaps LDS window
        float  pfs = 0.f;
        float2 pf2 = make_float2(0.f, 0.f);
        if (L0) { if (t + 2 < SS) pfs = *xps; xps += 1; }
        else    { if (t + 2 < SS) pf2 = *xp2; xp2 += 128; }

        // ax for this step
        float axA, axB;
        if (L0) { axA = fmaf(w0A, xcs, biasA); axB = fmaf(w0B, xcs, biasB); }
        else    { axA = xc2.x; axB = xc2.y; }

        // ---- four independent chains, depth 16 each (k-halves of 2 rows) ----
        ull a0a = pk2(axA, 0.f), a0b = pk2(0.f, 0.f);
        ull a1a = pk2(axB, 0.f), a1b = pk2(0.f, 0.f);
#pragma unroll
        for (int k = 0; k < 8; k++) {
            ulonglong2 hlo = hb[k];
            ulonglong2 hhi = hb[8 + k];
            a0a = ffma2(wA[2 * k], hlo.x, a0a);
            a0a = ffma2(wA[2 * k + 1], hlo.y, a0a);
            a0b = ffma2(wA[16 + 2 * k], hhi.x, a0b);
            a0b = ffma2(wA[17 + 2 * k], hhi.y, a0b);
            a1a = ffma2(wB[2 * k], hlo.x, a1a);
            a1a = ffma2(wB[2 * k + 1], hlo.y, a1a);
            a1b = ffma2(wB[16 + 2 * k], hhi.x, a1b);
            a1b = ffma2(wB[17 + 2 * k], hhi.y, a1b);
        }
        float l0, h0, l1, h1;
        upk2(a0a, l0, h0);
        upk2(a0b, l1, h1);
        float g0 = (l0 + h0) + (l1 + h1);
        upk2(a1a, l0, h0);
        upk2(a1b, l1, h1);
        float g1 = (l0 + h0) + (l1 + h1);

        // activations: p0 -> (i,f) sigmoids; p1 -> (g tanh, o sigmoid)
        float A0 = m0 * sig_(m0 * g0) - d0;
        float A1 = sig_(g1);

        // pair exchange
        float B0 = __shfl_xor_sync(0xffffffffu, A0, 1);
        float B1 = __shfl_xor_sync(0xffffffffu, A1, 1);
        float iv, fv, gv, ov;
        if (p == 0) { iv = A0; fv = A1; gv = B0; ov = B1; }
        else        { iv = B0; fv = B1; gv = A0; ov = A1; }

        // identical update in both lanes (deterministic)
        c = fv * c + iv * gv;
        float hv2 = ov * tanh_(c);

        // pre-barrier: ONLY the sh_h STS (BAR drains it)
        if (p == 0) {
            reinterpret_cast<float*>(sh_h[pr ^ 1][b])[hh] = hv2;
        }
        BATCH_BAR(b);   // this batch's 4 warps; h_t visible for t+1

        // post-barrier: global stores off the critical path
        if (p == 1) {
            hsout[((size_t)(b0 + b) * SS + t) * HH + hh] = hv2;
            if (t == SS - 1) {
                hn[(b0 + b) * HH + hh] = hv2;
                cn[(b0 + b) * HH + hh] = c;
            }
        }

        if (L0) { xcs = xns; xns = pfs; }
        else    { xc2 = xn2; xn2 = pf2; }
    }
}

// Final projection: thread-per-output, 16 consecutive LDG.128 per thread.
__global__ __launch_bounds__(256)
void proj_kernel(const float* __restrict__ hs, const float* __restrict__ Wlin,
                 const float* __restrict__ blin, float* __restrict__ y) {
    __shared__ float4 w[16];
    __shared__ float bsh;
    if (threadIdx.x < 16) w[threadIdx.x] = reinterpret_cast<const float4*>(Wlin)[threadIdx.x];
    if (threadIdx.x == 16) bsh = blin[0];
    __syncthreads();
    size_t o = (size_t)blockIdx.x * 256 + threadIdx.x;
    const float4* v = reinterpret_cast<const float4*>(hs + o * HH);
    float acc = 0.f;
#pragma unroll
    for (int k = 0; k < 16; k++) {
        float4 a = v[k];
        float4 b = w[k];
        acc += a.x * b.x + a.y * b.y + a.z * b.z + a.w * b.w;
    }
    y[o] = acc + bsh;
}

extern "C" void kernel_launch(void* const* d_in, const int* in_sizes, int n_in,
                              void* d_out, int out_size) {
    const float* x    = (const float*)d_in[0];
    const float* Wih0 = (const float*)d_in[1];
    const float* Whh0 = (const float*)d_in[2];
    const float* bih0 = (const float*)d_in[3];
    const float* bhh0 = (const float*)d_in[4];
    const float* Wih1 = (const float*)d_in[5];
    const float* Whh1 = (const float*)d_in[6];
    const float* bih1 = (const float*)d_in[7];
    const float* bhh1 = (const float*)d_in[8];
    const float* Wih2 = (const float*)d_in[9];
    const float* Whh2 = (const float*)d_in[10];
    const float* bih2 = (const float*)d_in[11];
    const float* bhh2 = (const float*)d_in[12];
    const float* Wlin = (const float*)d_in[13];
    const float* blin = (const float*)d_in[14];

    float* y  = (float*)d_out;                 // [B,S,1]
    float* hn = y + (size_t)BB * SS;           // [3,B,H]
    float* cn = hn + (size_t)3 * BB * HH;      // [3,B,H]

    float *buf0, *buf1, *xg;
    cudaGetSymbolAddress((void**)&buf0, g_buf0);
    cudaGetSymbolAddress((void**)&buf1, g_buf1);
    cudaGetSymbolAddress((void**)&xg,  g_xg);

    // Layer 0: inline scalar x (DIN=1)
    lstm_scan<true ><<<BB / 2, 256>>>(x, Wih0, Whh0, bih0, bhh0, buf0, hn, cn);
    // Layer 1: precompute interleaved xg, then h-only scan
    xgemm<<<BB, 256>>>(buf0, Wih1, bih1, bhh1, xg);
    lstm_scan<false><<<BB / 2, 256>>>(xg, Wih1, Whh1, bih1, bhh1, buf1,
                                      hn + BB * HH, cn + BB * HH);
    // Layer 2
    xgemm<<<BB, 256>>>(buf1, Wih2, bih2, bhh2, xg);
    lstm_scan<false><<<BB / 2, 256>>>(xg, Wih2, Whh2, bih2, bhh2, buf0,
                                      hn + 2 * BB * HH, cn + 2 * BB * HH);

    proj_kernel<<<(BB * SS) / 256, 256>>>(buf0, Wlin, blin, y);
}